// round 13
// baseline (speedup 1.0000x reference)
#include <cuda_runtime.h>

// LocalCorrRatio via shared-weight decomposition (two kernels, fence-free,
// low atomic contention).
// Kernel 1: block = shift-0 patch. Voxels as float4 {uT,vT,uP,vP}, u=K*y^2,
// v=-2K*y so w = ex2(fma(v,cb,u) + K*cb^2); stats recovered linearly.
// Per-sub-region bin partials ({4,5}^3 split at local coord 4); both shift-0
// etas staged in shared, ONE double atomicAdd into g_sum per block.
// Kernel 2: 125 blocks x 256; warp = one shifted patch (both directions),
// gathers 8 contributors' partials; block stages 8 warps' eta-sums in shared,
// ONE atomicAdd per block; acq_rel counter (125); last arriver writes out.

#define NPATCH 1000
#define W3 729
#define DIM 90
#define KEXP2 (-1386.4299343f)    // K = -961 * log2(e)
#define K2N   (2772.8598686f)     // -2K
#define MXS   (1.0f / 2772.8598686f)   // -1/(2K): y = v * MXS
#define KINV  (-1.0f / 1386.4299343f)  // 1/K: y^2 = u * KINV

__device__ float g_part[NPATCH * 8 * 4 * 32];   // [p][s][v][bin] v: SwA,SxA,SwB,SxB
__device__ float g_stats[NPATCH * 8 * 4];       // [p][s][{sumT,sumT2,sumP,sumP2}]
__device__ unsigned int g_count = 0;
__device__ double g_sum = 0.0;

__constant__ int cBASE[8]  = {0, 64, 144, 224, 324, 404, 504, 604};
__constant__ int cSPLIT[8] = {64, 144, 224, 324, 404, 504, 604, 729};

__device__ __forceinline__ float ex2(float x) {
    float r; asm("ex2.approx.f32 %0, %1;" : "=f"(r) : "f"(x)); return r;
}
__device__ __forceinline__ unsigned int atom_acqrel_add(unsigned int* a, unsigned int v) {
    unsigned int old;
    asm volatile("atom.acq_rel.gpu.global.add.u32 %0, [%1], %2;"
                 : "=r"(old) : "l"(a), "r"(v) : "memory");
    return old;
}

// Returns eta (valid in lane 0 only).
__device__ __forceinline__ float eta_value(int dir, float Sw, float Sx,
                                           float sT, float sT2, float sP, float sP2) {
    float sx  = (dir == 0) ? sT  : sP;
    float sx2 = (dir == 0) ? sT2 : sP2;
    float mean = sx * (1.0f / (float)W3);
    float var  = (sx2 - sx * sx * (1.0f / (float)W3)) * (1.0f / (float)(W3 - 1));
    float mi = Sx / (Sw + 1e-5f);
    float dm = mi - mean;
    float num = Sw * dm * dm;
    float den = Sw;
    #pragma unroll
    for (int o = 16; o; o >>= 1) {
        num += __shfl_xor_sync(0xffffffffu, num, o);
        den += __shfl_xor_sync(0xffffffffu, den, o);
    }
    return (num / den) / (var + 1e-5f);
}

__global__ __launch_bounds__(256, 8) void lcr_part_kernel(const float* __restrict__ yt,
                                                          const float* __restrict__ yp) {
    const int p = blockIdx.x;
    const int ph = p / 100;
    const int pw = (p / 10) % 10;
    const int pd = p % 10;

    __shared__ __align__(16) float4 uv[W3];    // {uT, vT, uP, vP}
    __shared__ float part_a[8][4][32];
    __shared__ float part_b[8][4][32];
    __shared__ float stats_sm[8][4];
    __shared__ float s_eta2[2];

    const int tid = threadIdx.x;
    const int warp = tid >> 5;
    const int lane = tid & 31;
    const float cb = (float)lane * (1.0f / 31.0f);
    const float cc = KEXP2 * cb * cb;

    // ---- Load patch into sub-region-major order; precompute u,v ----
    for (int idx = tid; idx < W3; idx += 256) {
        int i = idx / 81;
        int r = idx - i * 81;
        int j = r / 9;
        int k = r - j * 9;
        int g = ((ph * 9 + i) * DIM + (pw * 9 + j)) * DIM + (pd * 9 + k);
        float tv = yt[g];
        float pv = yp[g];
        int sh = (i >= 4), sw_ = (j >= 4), sd_ = (k >= 4);
        int s = (sh << 2) | (sw_ << 1) | sd_;
        int ii = i - (sh ? 4 : 0);
        int jj = j - (sw_ ? 4 : 0);
        int kk = k - (sd_ ? 4 : 0);
        int nw = sw_ ? 5 : 4;
        int nd = sd_ ? 5 : 4;
        int dest = cBASE[s] + (ii * nw + jj) * nd + kk;
        uv[dest] = make_float4(KEXP2 * tv * tv, K2N * tv,
                               KEXP2 * pv * pv, K2N * pv);
    }
    __syncthreads();

    // ---- Stats for sub-region s == warp (linear recovery from u,v) ----
    {
        int b0 = cBASE[warp];
        int b1 = (warp < 7) ? cBASE[warp + 1] : W3;
        float suT = 0.f, svT = 0.f, suP = 0.f, svP = 0.f;
        for (int idx = b0 + lane; idx < b1; idx += 32) {
            float4 q = uv[idx];
            suT += q.x;  svT += q.y;
            suP += q.z;  svP += q.w;
        }
        #pragma unroll
        for (int o = 16; o; o >>= 1) {
            suT += __shfl_xor_sync(0xffffffffu, suT, o);
            svT += __shfl_xor_sync(0xffffffffu, svT, o);
            suP += __shfl_xor_sync(0xffffffffu, suP, o);
            svP += __shfl_xor_sync(0xffffffffu, svP, o);
        }
        if (lane == 0) {
            stats_sm[warp][0] = svT * MXS;    // sum t
            stats_sm[warp][1] = suT * KINV;   // sum t^2
            stats_sm[warp][2] = svP * MXS;    // sum p
            stats_sm[warp][3] = suP * KINV;   // sum p^2
        }
    }

    // ---- Bin sums: lane = bin; warp range split at one static boundary ----
    {
        const int s1b = 92 * warp;
        const int s1e = cSPLIT[warp];
        float SwA = 0.f, SxA = 0.f, SwB = 0.f, SxB = 0.f;
        #pragma unroll 4
        for (int idx = s1b; idx < s1e; idx++) {
            float4 q = uv[idx];
            float wA = ex2(fmaf(q.w, cb, q.z) + cc);   // Y = pred
            float wB = ex2(fmaf(q.y, cb, q.x) + cc);   // Y = true
            SwA += wA;  SxA = fmaf(wA, q.y, SxA);      // x = true  (vT)
            SwB += wB;  SxB = fmaf(wB, q.w, SxB);      // x = pred  (vP)
        }
        part_a[warp][0][lane] = SwA;
        part_a[warp][1][lane] = SxA * MXS;
        part_a[warp][2][lane] = SwB;
        part_a[warp][3][lane] = SxB * MXS;

        if (warp < 7) {
            const int s2b = s1e;
            const int s2e = 92 * warp + 92;
            SwA = 0.f; SxA = 0.f; SwB = 0.f; SxB = 0.f;
            #pragma unroll 4
            for (int idx = s2b; idx < s2e; idx++) {
                float4 q = uv[idx];
                float wA = ex2(fmaf(q.w, cb, q.z) + cc);
                float wB = ex2(fmaf(q.y, cb, q.x) + cc);
                SwA += wA;  SxA = fmaf(wA, q.y, SxA);
                SwB += wB;  SxB = fmaf(wB, q.w, SxB);
            }
            part_b[warp + 1][0][lane] = SwA;
            part_b[warp + 1][1][lane] = SxA * MXS;
            part_b[warp + 1][2][lane] = SwB;
            part_b[warp + 1][3][lane] = SxB * MXS;
        }
    }
    __syncthreads();

    // ---- Combine per sub-region, publish to gmem ----
    {
        const int s = warp;
        float v0 = part_a[s][0][lane];
        float v1 = part_a[s][1][lane];
        float v2 = part_a[s][2][lane];
        float v3 = part_a[s][3][lane];
        if (s >= 1) {
            v0 += part_b[s][0][lane];
            v1 += part_b[s][1][lane];
            v2 += part_b[s][2][lane];
            v3 += part_b[s][3][lane];
        }
        part_a[s][0][lane] = v0;
        part_a[s][1][lane] = v1;
        part_a[s][2][lane] = v2;
        part_a[s][3][lane] = v3;
        int gb = ((p * 8 + s) * 4) * 32 + lane;
        g_part[gb]      = v0;
        g_part[gb + 32] = v1;
        g_part[gb + 64] = v2;
        g_part[gb + 96] = v3;
        if (lane < 4) g_stats[(p * 8 + s) * 4 + lane] = stats_sm[s][lane];
    }
    __syncthreads();

    // ---- Shift-0 etas (variants 0 and 1); ONE atomic per block ----
    if (warp < 2) {
        const int v0 = warp * 2;
        float Sw = 0.f, Sx = 0.f;
        #pragma unroll
        for (int s = 0; s < 8; s++) { Sw += part_a[s][v0][lane]; Sx += part_a[s][v0 + 1][lane]; }
        float sT = 0.f, sT2 = 0.f, sP = 0.f, sP2 = 0.f;
        #pragma unroll
        for (int s = 0; s < 8; s++) {
            sT += stats_sm[s][0]; sT2 += stats_sm[s][1];
            sP += stats_sm[s][2]; sP2 += stats_sm[s][3];
        }
        float e = eta_value(warp, Sw, Sx, sT, sT2, sP, sP2);
        if (lane == 0) s_eta2[warp] = e;
    }
    __syncthreads();
    if (tid == 0) {
        atomicAdd(&g_sum, (double)s_eta2[0] + (double)s_eta2[1]);
    }
}

__global__ __launch_bounds__(256) void lcr_final_kernel(float* __restrict__ out) {
    const int tid = threadIdx.x;
    const int warp = tid >> 5;
    const int lane = tid & 31;
    const int pt = blockIdx.x * 8 + warp;        // 125 blocks x 8 warps = 1000
    const int a = pt / 100;
    const int b = (pt / 10) % 10;
    const int c = pt % 10;

    __shared__ float s_eta[8];

    // g_part/g_stats from kernel 1: visible across the kernel boundary.
    float SwA = 0.f, SxA = 0.f, SwB = 0.f, SxB = 0.f;
    float sT = 0.f, sT2 = 0.f, sP = 0.f, sP2 = 0.f;
    #pragma unroll
    for (int cc = 0; cc < 8; cc++) {
        int dh = (cc >> 2) & 1, dw = (cc >> 1) & 1, dd = cc & 1;
        int qa = a + dh; if (qa >= 10) qa -= 10;
        int qb = b + dw; if (qb >= 10) qb -= 10;
        int qc = c + dd; if (qc >= 10) qc -= 10;
        int q = (qa * 10 + qb) * 10 + qc;
        int s = 7 - cc;                 // delta=0 -> hi half, delta=1 -> lo half
        int gb = ((q * 8 + s) * 4) * 32;
        SwA += g_part[gb + lane];
        SxA += g_part[gb + 32 + lane];
        SwB += g_part[gb + 64 + lane];
        SxB += g_part[gb + 96 + lane];
        int sb = (q * 8 + s) * 4;
        sT  += g_stats[sb + 0];
        sT2 += g_stats[sb + 1];
        sP  += g_stats[sb + 2];
        sP2 += g_stats[sb + 3];
    }
    float eA = eta_value(0, SwA, SxA, sT, sT2, sP, sP2);
    float eB = eta_value(1, SwB, SxB, sT, sT2, sP, sP2);
    if (lane == 0) s_eta[warp] = eA + eB;
    __syncthreads();

    // ---- One atomic per block, then acq_rel completion counter ----
    if (tid == 0) {
        double tot = 0.0;
        #pragma unroll
        for (int w = 0; w < 8; w++) tot += (double)s_eta[w];
        atomicAdd(&g_sum, tot);
        unsigned int old = atom_acqrel_add(&g_count, 1u);
        if (old == 125u - 1u) {
            double s = *((volatile double*)&g_sum);
            out[0] = (float)(-s / 12000.0);
            g_sum = 0.0;      // reset for next graph replay
            g_count = 0;
        }
    }
}

extern "C" void kernel_launch(void* const* d_in, const int* in_sizes, int n_in,
                              void* d_out, int out_size) {
    const float* y_true = (const float*)d_in[0];
    const float* y_pred = (const float*)d_in[1];
    float* out = (float*)d_out;
    lcr_part_kernel<<<NPATCH, 256>>>(y_true, y_pred);
    lcr_final_kernel<<<125, 256>>>(out);
}

// round 14
// speedup vs baseline: 1.0077x; 1.0077x over previous
#include <cuda_runtime.h>

// LocalCorrRatio via shared-weight decomposition, two kernels + PDL overlap.
// Kernel 1: block = shift-0 patch. Voxels as float4 {uT,vT,uP,vP}, u=K*y^2,
// v=-2K*y so w = ex2(fma(v,cb,u) + K*cb^2); stats recovered linearly.
// Per-sub-region bin partials ({4,5}^3 split at local coord 4); both shift-0
// etas -> ONE double atomicAdd into g_sum; then programmatic-launch trigger.
// Kernel 2 (PDL secondary): 125 blocks x 256; grid-dependency sync, then
// warp = one shifted patch (both directions), gathers 8 contributors'
// partials; ONE atomicAdd per block; acq_rel counter; last arriver writes out.

#define NPATCH 1000
#define W3 729
#define DIM 90
#define KEXP2 (-1386.4299343f)    // K = -961 * log2(e)
#define K2N   (2772.8598686f)     // -2K
#define MXS   (1.0f / 2772.8598686f)   // -1/(2K): y = v * MXS
#define KINV  (-1.0f / 1386.4299343f)  // 1/K: y^2 = u * KINV

__device__ float g_part[NPATCH * 8 * 4 * 32];   // [p][s][v][bin] v: SwA,SxA,SwB,SxB
__device__ float g_stats[NPATCH * 8 * 4];       // [p][s][{sumT,sumT2,sumP,sumP2}]
__device__ unsigned int g_count = 0;
__device__ double g_sum = 0.0;

__constant__ int cBASE[8]  = {0, 64, 144, 224, 324, 404, 504, 604};
__constant__ int cSPLIT[8] = {64, 144, 224, 324, 404, 504, 604, 729};

__device__ __forceinline__ float ex2(float x) {
    float r; asm("ex2.approx.f32 %0, %1;" : "=f"(r) : "f"(x)); return r;
}
__device__ __forceinline__ unsigned int atom_acqrel_add(unsigned int* a, unsigned int v) {
    unsigned int old;
    asm volatile("atom.acq_rel.gpu.global.add.u32 %0, [%1], %2;"
                 : "=r"(old) : "l"(a), "r"(v) : "memory");
    return old;
}

// Returns eta (valid in lane 0 only).
__device__ __forceinline__ float eta_value(int dir, float Sw, float Sx,
                                           float sT, float sT2, float sP, float sP2) {
    float sx  = (dir == 0) ? sT  : sP;
    float sx2 = (dir == 0) ? sT2 : sP2;
    float mean = sx * (1.0f / (float)W3);
    float var  = (sx2 - sx * sx * (1.0f / (float)W3)) * (1.0f / (float)(W3 - 1));
    float mi = Sx / (Sw + 1e-5f);
    float dm = mi - mean;
    float num = Sw * dm * dm;
    float den = Sw;
    #pragma unroll
    for (int o = 16; o; o >>= 1) {
        num += __shfl_xor_sync(0xffffffffu, num, o);
        den += __shfl_xor_sync(0xffffffffu, den, o);
    }
    return (num / den) / (var + 1e-5f);
}

__global__ __launch_bounds__(256, 8) void lcr_part_kernel(const float* __restrict__ yt,
                                                          const float* __restrict__ yp) {
    const int p = blockIdx.x;
    const int ph = p / 100;
    const int pw = (p / 10) % 10;
    const int pd = p % 10;

    __shared__ __align__(16) float4 uv[W3];    // {uT, vT, uP, vP}
    __shared__ float part_a[8][4][32];
    __shared__ float part_b[8][4][32];
    __shared__ float stats_sm[8][4];
    __shared__ float s_eta2[2];

    const int tid = threadIdx.x;
    const int warp = tid >> 5;
    const int lane = tid & 31;
    const float cb = (float)lane * (1.0f / 31.0f);
    const float cc = KEXP2 * cb * cb;

    // ---- Load patch into sub-region-major order; precompute u,v ----
    for (int idx = tid; idx < W3; idx += 256) {
        int i = idx / 81;
        int r = idx - i * 81;
        int j = r / 9;
        int k = r - j * 9;
        int g = ((ph * 9 + i) * DIM + (pw * 9 + j)) * DIM + (pd * 9 + k);
        float tv = yt[g];
        float pv = yp[g];
        int sh = (i >= 4), sw_ = (j >= 4), sd_ = (k >= 4);
        int s = (sh << 2) | (sw_ << 1) | sd_;
        int ii = i - (sh ? 4 : 0);
        int jj = j - (sw_ ? 4 : 0);
        int kk = k - (sd_ ? 4 : 0);
        int nw = sw_ ? 5 : 4;
        int nd = sd_ ? 5 : 4;
        int dest = cBASE[s] + (ii * nw + jj) * nd + kk;
        uv[dest] = make_float4(KEXP2 * tv * tv, K2N * tv,
                               KEXP2 * pv * pv, K2N * pv);
    }
    __syncthreads();

    // ---- Stats for sub-region s == warp (linear recovery from u,v) ----
    {
        int b0 = cBASE[warp];
        int b1 = (warp < 7) ? cBASE[warp + 1] : W3;
        float suT = 0.f, svT = 0.f, suP = 0.f, svP = 0.f;
        for (int idx = b0 + lane; idx < b1; idx += 32) {
            float4 q = uv[idx];
            suT += q.x;  svT += q.y;
            suP += q.z;  svP += q.w;
        }
        #pragma unroll
        for (int o = 16; o; o >>= 1) {
            suT += __shfl_xor_sync(0xffffffffu, suT, o);
            svT += __shfl_xor_sync(0xffffffffu, svT, o);
            suP += __shfl_xor_sync(0xffffffffu, suP, o);
            svP += __shfl_xor_sync(0xffffffffu, svP, o);
        }
        if (lane == 0) {
            stats_sm[warp][0] = svT * MXS;    // sum t
            stats_sm[warp][1] = suT * KINV;   // sum t^2
            stats_sm[warp][2] = svP * MXS;    // sum p
            stats_sm[warp][3] = suP * KINV;   // sum p^2
        }
    }

    // ---- Bin sums: lane = bin; warp range split at one static boundary ----
    {
        const int s1b = 92 * warp;
        const int s1e = cSPLIT[warp];
        float SwA = 0.f, SxA = 0.f, SwB = 0.f, SxB = 0.f;
        #pragma unroll 4
        for (int idx = s1b; idx < s1e; idx++) {
            float4 q = uv[idx];
            float wA = ex2(fmaf(q.w, cb, q.z) + cc);   // Y = pred
            float wB = ex2(fmaf(q.y, cb, q.x) + cc);   // Y = true
            SwA += wA;  SxA = fmaf(wA, q.y, SxA);      // x = true  (vT)
            SwB += wB;  SxB = fmaf(wB, q.w, SxB);      // x = pred  (vP)
        }
        part_a[warp][0][lane] = SwA;
        part_a[warp][1][lane] = SxA * MXS;
        part_a[warp][2][lane] = SwB;
        part_a[warp][3][lane] = SxB * MXS;

        if (warp < 7) {
            const int s2b = s1e;
            const int s2e = 92 * warp + 92;
            SwA = 0.f; SxA = 0.f; SwB = 0.f; SxB = 0.f;
            #pragma unroll 4
            for (int idx = s2b; idx < s2e; idx++) {
                float4 q = uv[idx];
                float wA = ex2(fmaf(q.w, cb, q.z) + cc);
                float wB = ex2(fmaf(q.y, cb, q.x) + cc);
                SwA += wA;  SxA = fmaf(wA, q.y, SxA);
                SwB += wB;  SxB = fmaf(wB, q.w, SxB);
            }
            part_b[warp + 1][0][lane] = SwA;
            part_b[warp + 1][1][lane] = SxA * MXS;
            part_b[warp + 1][2][lane] = SwB;
            part_b[warp + 1][3][lane] = SxB * MXS;
        }
    }
    __syncthreads();

    // ---- Combine per sub-region, publish to gmem ----
    {
        const int s = warp;
        float v0 = part_a[s][0][lane];
        float v1 = part_a[s][1][lane];
        float v2 = part_a[s][2][lane];
        float v3 = part_a[s][3][lane];
        if (s >= 1) {
            v0 += part_b[s][0][lane];
            v1 += part_b[s][1][lane];
            v2 += part_b[s][2][lane];
            v3 += part_b[s][3][lane];
        }
        part_a[s][0][lane] = v0;
        part_a[s][1][lane] = v1;
        part_a[s][2][lane] = v2;
        part_a[s][3][lane] = v3;
        int gb = ((p * 8 + s) * 4) * 32 + lane;
        g_part[gb]      = v0;
        g_part[gb + 32] = v1;
        g_part[gb + 64] = v2;
        g_part[gb + 96] = v3;
        if (lane < 4) g_stats[(p * 8 + s) * 4 + lane] = stats_sm[s][lane];
    }
    __syncthreads();

    // ---- Shift-0 etas (variants 0 and 1); ONE atomic per block ----
    if (warp < 2) {
        const int v0 = warp * 2;
        float Sw = 0.f, Sx = 0.f;
        #pragma unroll
        for (int s = 0; s < 8; s++) { Sw += part_a[s][v0][lane]; Sx += part_a[s][v0 + 1][lane]; }
        float sT = 0.f, sT2 = 0.f, sP = 0.f, sP2 = 0.f;
        #pragma unroll
        for (int s = 0; s < 8; s++) {
            sT += stats_sm[s][0]; sT2 += stats_sm[s][1];
            sP += stats_sm[s][2]; sP2 += stats_sm[s][3];
        }
        float e = eta_value(warp, Sw, Sx, sT, sT2, sP, sP2);
        if (lane == 0) s_eta2[warp] = e;
    }
    __syncthreads();
    if (tid == 0) {
        atomicAdd(&g_sum, (double)s_eta2[0] + (double)s_eta2[1]);
        // All of this block's partials, stats, and g_sum contribution are now
        // issued; signal the dependent kernel. (Trigger fires when all CTAs
        // have triggered or exited.)
        cudaTriggerProgrammaticLaunchCompletion();
    }
}

__global__ __launch_bounds__(256) void lcr_final_kernel(float* __restrict__ out) {
    const int tid = threadIdx.x;
    const int warp = tid >> 5;
    const int lane = tid & 31;
    const int pt = blockIdx.x * 8 + warp;        // 125 blocks x 8 warps = 1000
    const int a = pt / 100;
    const int b = (pt / 10) % 10;
    const int c = pt % 10;

    __shared__ float s_eta[8];

    // Overlap-able prologue done; wait for the primary grid's data.
    cudaGridDependencySynchronize();

    float SwA = 0.f, SxA = 0.f, SwB = 0.f, SxB = 0.f;
    float sT = 0.f, sT2 = 0.f, sP = 0.f, sP2 = 0.f;
    #pragma unroll
    for (int cc = 0; cc < 8; cc++) {
        int dh = (cc >> 2) & 1, dw = (cc >> 1) & 1, dd = cc & 1;
        int qa = a + dh; if (qa >= 10) qa -= 10;
        int qb = b + dw; if (qb >= 10) qb -= 10;
        int qc = c + dd; if (qc >= 10) qc -= 10;
        int q = (qa * 10 + qb) * 10 + qc;
        int s = 7 - cc;                 // delta=0 -> hi half, delta=1 -> lo half
        int gb = ((q * 8 + s) * 4) * 32;
        SwA += g_part[gb + lane];
        SxA += g_part[gb + 32 + lane];
        SwB += g_part[gb + 64 + lane];
        SxB += g_part[gb + 96 + lane];
        int sb = (q * 8 + s) * 4;
        sT  += g_stats[sb + 0];
        sT2 += g_stats[sb + 1];
        sP  += g_stats[sb + 2];
        sP2 += g_stats[sb + 3];
    }

    // Both etas with one fused 4-value shuffle chain.
    {
        float meanA = sT * (1.0f / (float)W3);
        float varA  = (sT2 - sT * sT * (1.0f / (float)W3)) * (1.0f / (float)(W3 - 1));
        float meanB = sP * (1.0f / (float)W3);
        float varB  = (sP2 - sP * sP * (1.0f / (float)W3)) * (1.0f / (float)(W3 - 1));
        float miA = SxA / (SwA + 1e-5f);
        float miB = SxB / (SwB + 1e-5f);
        float dA = miA - meanA;
        float dB = miB - meanB;
        float numA = SwA * dA * dA, denA = SwA;
        float numB = SwB * dB * dB, denB = SwB;
        #pragma unroll
        for (int o = 16; o; o >>= 1) {
            numA += __shfl_xor_sync(0xffffffffu, numA, o);
            denA += __shfl_xor_sync(0xffffffffu, denA, o);
            numB += __shfl_xor_sync(0xffffffffu, numB, o);
            denB += __shfl_xor_sync(0xffffffffu, denB, o);
        }
        if (lane == 0)
            s_eta[warp] = (numA / denA) / (varA + 1e-5f)
                        + (numB / denB) / (varB + 1e-5f);
    }
    __syncthreads();

    // ---- One atomic per block, then acq_rel completion counter ----
    if (tid == 0) {
        double tot = 0.0;
        #pragma unroll
        for (int w = 0; w < 8; w++) tot += (double)s_eta[w];
        atomicAdd(&g_sum, tot);
        unsigned int old = atom_acqrel_add(&g_count, 1u);
        if (old == 125u - 1u) {
            double s = *((volatile double*)&g_sum);
            out[0] = (float)(-s / 12000.0);
            g_sum = 0.0;      // reset for next graph replay
            g_count = 0;
        }
    }
}

extern "C" void kernel_launch(void* const* d_in, const int* in_sizes, int n_in,
                              void* d_out, int out_size) {
    const float* y_true = (const float*)d_in[0];
    const float* y_pred = (const float*)d_in[1];
    float* out = (float*)d_out;

    lcr_part_kernel<<<NPATCH, 256>>>(y_true, y_pred);

    // Secondary kernel with programmatic dependent launch: its blocks may
    // launch while lcr_part_kernel drains; cudaGridDependencySynchronize()
    // inside guards the data reads.
    cudaLaunchConfig_t cfg = {};
    cfg.gridDim = dim3(125, 1, 1);
    cfg.blockDim = dim3(256, 1, 1);
    cfg.dynamicSmemBytes = 0;
    cudaLaunchAttribute attrs[1];
    attrs[0].id = cudaLaunchAttributeProgrammaticStreamSerialization;
    attrs[0].val.programmaticStreamSerializationAllowed = 1;
    cfg.attrs = attrs;
    cfg.numAttrs = 1;
    cudaLaunchKernelEx(&cfg, lcr_final_kernel, out);
}

// round 15
// speedup vs baseline: 1.0837x; 1.0755x over previous
#include <cuda_runtime.h>

// LocalCorrRatio via shared-weight decomposition, two kernels + PDL.
// CONSUMER-MAJOR partial layout: k1 block p writes sub-region s's partial
// into the record of the shifted patch pt that consumes it (slot cc=7-s), so
// k2's gather per patch is one contiguous 4KB read (coalesced streaming).
// Kernel 1: block = shift-0 patch; float4 {uT,vT,uP,vP} voxels, u=K*y^2,
// v=-2K*y, w = ex2(fma(v,cb,u)+K*cb^2); stats linear-recovered; shift-0 etas
// -> ONE double atomicAdd; programmatic trigger.
// Kernel 2: 125x256; warp = shifted patch (both dirs); contiguous gather;
// ONE atomicAdd per block; acq_rel counter (125); last arriver writes out.

#define NPATCH 1000
#define W3 729
#define DIM 90
#define KEXP2 (-1386.4299343f)    // K = -961 * log2(e)
#define K2N   (2772.8598686f)     // -2K
#define MXS   (1.0f / 2772.8598686f)   // -1/(2K): y = v * MXS
#define KINV  (-1.0f / 1386.4299343f)  // 1/K: y^2 = u * KINV

// Consumer-major: [pt][cc][v][bin]  (pt = consuming shifted patch, cc = slot)
__device__ float g_part[NPATCH * 8 * 4 * 32];
__device__ float g_stats[NPATCH * 8 * 4];       // [pt][cc][{sumT,sumT2,sumP,sumP2}]
__device__ unsigned int g_count = 0;
__device__ double g_sum = 0.0;

__constant__ int cBASE[8]  = {0, 64, 144, 224, 324, 404, 504, 604};
__constant__ int cSPLIT[8] = {64, 144, 224, 324, 404, 504, 604, 729};

__device__ __forceinline__ float ex2(float x) {
    float r; asm("ex2.approx.f32 %0, %1;" : "=f"(r) : "f"(x)); return r;
}
__device__ __forceinline__ unsigned int atom_acqrel_add(unsigned int* a, unsigned int v) {
    unsigned int old;
    asm volatile("atom.acq_rel.gpu.global.add.u32 %0, [%1], %2;"
                 : "=r"(old) : "l"(a), "r"(v) : "memory");
    return old;
}

// Returns eta (valid in lane 0 only).
__device__ __forceinline__ float eta_value(int dir, float Sw, float Sx,
                                           float sT, float sT2, float sP, float sP2) {
    float sx  = (dir == 0) ? sT  : sP;
    float sx2 = (dir == 0) ? sT2 : sP2;
    float mean = sx * (1.0f / (float)W3);
    float var  = (sx2 - sx * sx * (1.0f / (float)W3)) * (1.0f / (float)(W3 - 1));
    float mi = Sx / (Sw + 1e-5f);
    float dm = mi - mean;
    float num = Sw * dm * dm;
    float den = Sw;
    #pragma unroll
    for (int o = 16; o; o >>= 1) {
        num += __shfl_xor_sync(0xffffffffu, num, o);
        den += __shfl_xor_sync(0xffffffffu, den, o);
    }
    return (num / den) / (var + 1e-5f);
}

__global__ __launch_bounds__(256, 8) void lcr_part_kernel(const float* __restrict__ yt,
                                                          const float* __restrict__ yp) {
    const int p = blockIdx.x;
    const int ph = p / 100;
    const int pw = (p / 10) % 10;
    const int pd = p % 10;

    __shared__ __align__(16) float4 uv[W3];    // {uT, vT, uP, vP}
    __shared__ float part_a[8][4][32];
    __shared__ float part_b[8][4][32];
    __shared__ float stats_sm[8][4];
    __shared__ float s_eta2[2];

    const int tid = threadIdx.x;
    const int warp = tid >> 5;
    const int lane = tid & 31;
    const float cb = (float)lane * (1.0f / 31.0f);
    const float cc = KEXP2 * cb * cb;

    // ---- Load patch into sub-region-major order; precompute u,v ----
    for (int idx = tid; idx < W3; idx += 256) {
        int i = idx / 81;
        int r = idx - i * 81;
        int j = r / 9;
        int k = r - j * 9;
        int g = ((ph * 9 + i) * DIM + (pw * 9 + j)) * DIM + (pd * 9 + k);
        float tv = yt[g];
        float pv = yp[g];
        int sh = (i >= 4), sw_ = (j >= 4), sd_ = (k >= 4);
        int s = (sh << 2) | (sw_ << 1) | sd_;
        int ii = i - (sh ? 4 : 0);
        int jj = j - (sw_ ? 4 : 0);
        int kk = k - (sd_ ? 4 : 0);
        int nw = sw_ ? 5 : 4;
        int nd = sd_ ? 5 : 4;
        int dest = cBASE[s] + (ii * nw + jj) * nd + kk;
        uv[dest] = make_float4(KEXP2 * tv * tv, K2N * tv,
                               KEXP2 * pv * pv, K2N * pv);
    }
    __syncthreads();

    // ---- Stats for sub-region s == warp (linear recovery from u,v) ----
    {
        int b0 = cBASE[warp];
        int b1 = (warp < 7) ? cBASE[warp + 1] : W3;
        float suT = 0.f, svT = 0.f, suP = 0.f, svP = 0.f;
        for (int idx = b0 + lane; idx < b1; idx += 32) {
            float4 q = uv[idx];
            suT += q.x;  svT += q.y;
            suP += q.z;  svP += q.w;
        }
        #pragma unroll
        for (int o = 16; o; o >>= 1) {
            suT += __shfl_xor_sync(0xffffffffu, suT, o);
            svT += __shfl_xor_sync(0xffffffffu, svT, o);
            suP += __shfl_xor_sync(0xffffffffu, suP, o);
            svP += __shfl_xor_sync(0xffffffffu, svP, o);
        }
        if (lane == 0) {
            stats_sm[warp][0] = svT * MXS;    // sum t
            stats_sm[warp][1] = suT * KINV;   // sum t^2
            stats_sm[warp][2] = svP * MXS;    // sum p
            stats_sm[warp][3] = suP * KINV;   // sum p^2
        }
    }

    // ---- Bin sums: lane = bin; warp range split at one static boundary ----
    {
        const int s1b = 92 * warp;
        const int s1e = cSPLIT[warp];
        float SwA = 0.f, SxA = 0.f, SwB = 0.f, SxB = 0.f;
        #pragma unroll 4
        for (int idx = s1b; idx < s1e; idx++) {
            float4 q = uv[idx];
            float wA = ex2(fmaf(q.w, cb, q.z) + cc);   // Y = pred
            float wB = ex2(fmaf(q.y, cb, q.x) + cc);   // Y = true
            SwA += wA;  SxA = fmaf(wA, q.y, SxA);      // x = true  (vT)
            SwB += wB;  SxB = fmaf(wB, q.w, SxB);      // x = pred  (vP)
        }
        part_a[warp][0][lane] = SwA;
        part_a[warp][1][lane] = SxA * MXS;
        part_a[warp][2][lane] = SwB;
        part_a[warp][3][lane] = SxB * MXS;

        if (warp < 7) {
            const int s2b = s1e;
            const int s2e = 92 * warp + 92;
            SwA = 0.f; SxA = 0.f; SwB = 0.f; SxB = 0.f;
            #pragma unroll 4
            for (int idx = s2b; idx < s2e; idx++) {
                float4 q = uv[idx];
                float wA = ex2(fmaf(q.w, cb, q.z) + cc);
                float wB = ex2(fmaf(q.y, cb, q.x) + cc);
                SwA += wA;  SxA = fmaf(wA, q.y, SxA);
                SwB += wB;  SxB = fmaf(wB, q.w, SxB);
            }
            part_b[warp + 1][0][lane] = SwA;
            part_b[warp + 1][1][lane] = SxA * MXS;
            part_b[warp + 1][2][lane] = SwB;
            part_b[warp + 1][3][lane] = SxB * MXS;
        }
    }
    __syncthreads();

    // ---- Combine per sub-region, publish CONSUMER-MAJOR to gmem ----
    {
        const int s = warp;
        float v0 = part_a[s][0][lane];
        float v1 = part_a[s][1][lane];
        float v2 = part_a[s][2][lane];
        float v3 = part_a[s][3][lane];
        if (s >= 1) {
            v0 += part_b[s][0][lane];
            v1 += part_b[s][1][lane];
            v2 += part_b[s][2][lane];
            v3 += part_b[s][3][lane];
        }
        part_a[s][0][lane] = v0;
        part_a[s][1][lane] = v1;
        part_a[s][2][lane] = v2;
        part_a[s][3][lane] = v3;

        // Consuming shifted patch for sub-region s: slot cc2 = 7 - s,
        // pt = p shifted back by cc2's delta bits.
        int cc2 = 7 - s;
        int dh = (cc2 >> 2) & 1, dw = (cc2 >> 1) & 1, dd = cc2 & 1;
        int pa = ph - dh; if (pa < 0) pa += 10;
        int pb = pw - dw; if (pb < 0) pb += 10;
        int pc = pd - dd; if (pc < 0) pc += 10;
        int pt = (pa * 10 + pb) * 10 + pc;

        int gb = ((pt * 8 + cc2) * 4) * 32 + lane;
        g_part[gb]      = v0;
        g_part[gb + 32] = v1;
        g_part[gb + 64] = v2;
        g_part[gb + 96] = v3;
        if (lane < 4) g_stats[(pt * 8 + cc2) * 4 + lane] = stats_sm[s][lane];
    }
    __syncthreads();

    // ---- Shift-0 etas (variants 0 and 1); ONE atomic per block ----
    if (warp < 2) {
        const int v0 = warp * 2;
        float Sw = 0.f, Sx = 0.f;
        #pragma unroll
        for (int s = 0; s < 8; s++) { Sw += part_a[s][v0][lane]; Sx += part_a[s][v0 + 1][lane]; }
        float sT = 0.f, sT2 = 0.f, sP = 0.f, sP2 = 0.f;
        #pragma unroll
        for (int s = 0; s < 8; s++) {
            sT += stats_sm[s][0]; sT2 += stats_sm[s][1];
            sP += stats_sm[s][2]; sP2 += stats_sm[s][3];
        }
        float e = eta_value(warp, Sw, Sx, sT, sT2, sP, sP2);
        if (lane == 0) s_eta2[warp] = e;
    }
    __syncthreads();
    if (tid == 0) {
        atomicAdd(&g_sum, (double)s_eta2[0] + (double)s_eta2[1]);
        cudaTriggerProgrammaticLaunchCompletion();
    }
}

__global__ __launch_bounds__(256) void lcr_final_kernel(float* __restrict__ out) {
    const int tid = threadIdx.x;
    const int warp = tid >> 5;
    const int lane = tid & 31;
    const int pt = blockIdx.x * 8 + warp;        // 125 blocks x 8 warps = 1000

    __shared__ float s_eta[8];

    cudaGridDependencySynchronize();

    // Contiguous consumer-major gather: 8 slots x 4 vectors x 32 lanes.
    float SwA = 0.f, SxA = 0.f, SwB = 0.f, SxB = 0.f;
    float sT = 0.f, sT2 = 0.f, sP = 0.f, sP2 = 0.f;
    const float* base = &g_part[(pt * 8) * 4 * 32];
    #pragma unroll
    for (int cc = 0; cc < 8; cc++) {
        const float* rec = base + cc * 128;
        SwA += rec[lane];
        SxA += rec[32 + lane];
        SwB += rec[64 + lane];
        SxB += rec[96 + lane];
        int sb = (pt * 8 + cc) * 4;
        sT  += g_stats[sb + 0];
        sT2 += g_stats[sb + 1];
        sP  += g_stats[sb + 2];
        sP2 += g_stats[sb + 3];
    }

    // Both etas with one fused 4-value shuffle chain.
    {
        float meanA = sT * (1.0f / (float)W3);
        float varA  = (sT2 - sT * sT * (1.0f / (float)W3)) * (1.0f / (float)(W3 - 1));
        float meanB = sP * (1.0f / (float)W3);
        float varB  = (sP2 - sP * sP * (1.0f / (float)W3)) * (1.0f / (float)(W3 - 1));
        float miA = SxA / (SwA + 1e-5f);
        float miB = SxB / (SwB + 1e-5f);
        float dA = miA - meanA;
        float dB = miB - meanB;
        float numA = SwA * dA * dA, denA = SwA;
        float numB = SwB * dB * dB, denB = SwB;
        #pragma unroll
        for (int o = 16; o; o >>= 1) {
            numA += __shfl_xor_sync(0xffffffffu, numA, o);
            denA += __shfl_xor_sync(0xffffffffu, denA, o);
            numB += __shfl_xor_sync(0xffffffffu, numB, o);
            denB += __shfl_xor_sync(0xffffffffu, denB, o);
        }
        if (lane == 0)
            s_eta[warp] = (numA / denA) / (varA + 1e-5f)
                        + (numB / denB) / (varB + 1e-5f);
    }
    __syncthreads();

    // ---- One atomic per block, then acq_rel completion counter ----
    if (tid == 0) {
        double tot = 0.0;
        #pragma unroll
        for (int w = 0; w < 8; w++) tot += (double)s_eta[w];
        atomicAdd(&g_sum, tot);
        unsigned int old = atom_acqrel_add(&g_count, 1u);
        if (old == 125u - 1u) {
            double s = *((volatile double*)&g_sum);
            out[0] = (float)(-s / 12000.0);
            g_sum = 0.0;      // reset for next graph replay
            g_count = 0;
        }
    }
}

extern "C" void kernel_launch(void* const* d_in, const int* in_sizes, int n_in,
                              void* d_out, int out_size) {
    const float* y_true = (const float*)d_in[0];
    const float* y_pred = (const float*)d_in[1];
    float* out = (float*)d_out;

    lcr_part_kernel<<<NPATCH, 256>>>(y_true, y_pred);

    cudaLaunchConfig_t cfg = {};
    cfg.gridDim = dim3(125, 1, 1);
    cfg.blockDim = dim3(256, 1, 1);
    cfg.dynamicSmemBytes = 0;
    cudaLaunchAttribute attrs[1];
    attrs[0].id = cudaLaunchAttributeProgrammaticStreamSerialization;
    attrs[0].val.programmaticStreamSerializationAllowed = 1;
    cfg.attrs = attrs;
    cfg.numAttrs = 1;
    cudaLaunchKernelEx(&cfg, lcr_final_kernel, out);
}

// round 16
// speedup vs baseline: 1.1574x; 1.0680x over previous
#include <cuda_runtime.h>
#include <cuda_fp16.h>

// LocalCorrRatio, two kernels + PDL, consumer-major records, f16x2 exp.
// Kernel 1: block = shift-0 patch; float4 {uT,vT,uP,vP}, u=K*y^2, v=-2K*y;
// BOTH directions' Parzen weights from ONE ex2.approx.f16x2 per voxel
// (args fp32, accumulators fp32). Per-sub-region partials published into the
// consuming shifted patch's contiguous record [pt][cc][5][32] (row 4 = stats).
// Shift-0 etas -> ONE double atomicAdd; programmatic trigger.
// Kernel 2: 125x256; warp = shifted patch; one contiguous 5KB gather; ONE
// atomicAdd per block; acq_rel counter (125); last arriver writes out.

#define NPATCH 1000
#define W3 729
#define DIM 90
#define KEXP2 (-1386.4299343f)    // K = -961 * log2(e)
#define K2N   (2772.8598686f)     // -2K
#define MXS   (1.0f / 2772.8598686f)   // -1/(2K): y = v * MXS
#define KINV  (-1.0f / 1386.4299343f)  // 1/K: y^2 = u * KINV

// Consumer-major records: [pt][cc][5][32]; rows 0-3 = SwA,SxA,SwB,SxB bins,
// row 4 lanes 0-3 = {sumT, sumT2, sumP, sumP2}.
__device__ float g_rec[NPATCH * 8 * 5 * 32];
__device__ unsigned int g_count = 0;
__device__ double g_sum = 0.0;

__constant__ int cBASE[8]  = {0, 64, 144, 224, 324, 404, 504, 604};
__constant__ int cSPLIT[8] = {64, 144, 224, 324, 404, 504, 604, 729};

__device__ __forceinline__ unsigned int atom_acqrel_add(unsigned int* a, unsigned int v) {
    unsigned int old;
    asm volatile("atom.acq_rel.gpu.global.add.u32 %0, [%1], %2;"
                 : "=r"(old) : "l"(a), "r"(v) : "memory");
    return old;
}

// Two exp2's with one MUFU op: returns {2^la, 2^ha} (computed in f16).
__device__ __forceinline__ void ex2_pair(float la, float ha, float& lw, float& hw) {
    unsigned int p;
    asm("cvt.rn.f16x2.f32 %0, %1, %2;" : "=r"(p) : "f"(ha), "f"(la));
    asm("ex2.approx.f16x2 %0, %0;" : "+r"(p));
    asm("{\n\t.reg .b16 l, h;\n\t"
        "mov.b32 {l, h}, %2;\n\t"
        "cvt.f32.f16 %0, l;\n\t"
        "cvt.f32.f16 %1, h;\n\t}"
        : "=f"(lw), "=f"(hw) : "r"(p));
}

// Returns eta (valid in lane 0 only).
__device__ __forceinline__ float eta_value(int dir, float Sw, float Sx,
                                           float sT, float sT2, float sP, float sP2) {
    float sx  = (dir == 0) ? sT  : sP;
    float sx2 = (dir == 0) ? sT2 : sP2;
    float mean = sx * (1.0f / (float)W3);
    float var  = (sx2 - sx * sx * (1.0f / (float)W3)) * (1.0f / (float)(W3 - 1));
    float mi = Sx / (Sw + 1e-5f);
    float dm = mi - mean;
    float num = Sw * dm * dm;
    float den = Sw;
    #pragma unroll
    for (int o = 16; o; o >>= 1) {
        num += __shfl_xor_sync(0xffffffffu, num, o);
        den += __shfl_xor_sync(0xffffffffu, den, o);
    }
    return (num / den) / (var + 1e-5f);
}

__global__ __launch_bounds__(256, 8) void lcr_part_kernel(const float* __restrict__ yt,
                                                          const float* __restrict__ yp) {
    const int p = blockIdx.x;
    const int ph = p / 100;
    const int pw = (p / 10) % 10;
    const int pd = p % 10;

    __shared__ __align__(16) float4 uv[W3];    // {uT, vT, uP, vP}
    __shared__ float part_a[8][4][32];
    __shared__ float part_b[8][4][32];
    __shared__ float stats_sm[8][4];
    __shared__ float s_eta2[2];

    const int tid = threadIdx.x;
    const int warp = tid >> 5;
    const int lane = tid & 31;
    const float cb = (float)lane * (1.0f / 31.0f);
    const float cc = KEXP2 * cb * cb;

    // ---- Load patch into sub-region-major order; precompute u,v ----
    for (int idx = tid; idx < W3; idx += 256) {
        int i = idx / 81;
        int r = idx - i * 81;
        int j = r / 9;
        int k = r - j * 9;
        int g = ((ph * 9 + i) * DIM + (pw * 9 + j)) * DIM + (pd * 9 + k);
        float tv = yt[g];
        float pv = yp[g];
        int sh = (i >= 4), sw_ = (j >= 4), sd_ = (k >= 4);
        int s = (sh << 2) | (sw_ << 1) | sd_;
        int ii = i - (sh ? 4 : 0);
        int jj = j - (sw_ ? 4 : 0);
        int kk = k - (sd_ ? 4 : 0);
        int nw = sw_ ? 5 : 4;
        int nd = sd_ ? 5 : 4;
        int dest = cBASE[s] + (ii * nw + jj) * nd + kk;
        uv[dest] = make_float4(KEXP2 * tv * tv, K2N * tv,
                               KEXP2 * pv * pv, K2N * pv);
    }
    __syncthreads();

    // ---- Stats for sub-region s == warp (linear recovery from u,v) ----
    {
        int b0 = cBASE[warp];
        int b1 = (warp < 7) ? cBASE[warp + 1] : W3;
        float suT = 0.f, svT = 0.f, suP = 0.f, svP = 0.f;
        for (int idx = b0 + lane; idx < b1; idx += 32) {
            float4 q = uv[idx];
            suT += q.x;  svT += q.y;
            suP += q.z;  svP += q.w;
        }
        #pragma unroll
        for (int o = 16; o; o >>= 1) {
            suT += __shfl_xor_sync(0xffffffffu, suT, o);
            svT += __shfl_xor_sync(0xffffffffu, svT, o);
            suP += __shfl_xor_sync(0xffffffffu, suP, o);
            svP += __shfl_xor_sync(0xffffffffu, svP, o);
        }
        if (lane == 0) {
            stats_sm[warp][0] = svT * MXS;    // sum t
            stats_sm[warp][1] = suT * KINV;   // sum t^2
            stats_sm[warp][2] = svP * MXS;    // sum p
            stats_sm[warp][3] = suP * KINV;   // sum p^2
        }
    }

    // ---- Bin sums: lane = bin; warp range split at one static boundary.
    //      One f16x2 MUFU per voxel computes both directions' weights. ----
    {
        const int s1b = 92 * warp;
        const int s1e = cSPLIT[warp];
        float SwA = 0.f, SxA = 0.f, SwB = 0.f, SxB = 0.f;
        #pragma unroll 4
        for (int idx = s1b; idx < s1e; idx++) {
            float4 q = uv[idx];
            float argA = fmaf(q.w, cb, q.z) + cc;   // Y = pred
            float argB = fmaf(q.y, cb, q.x) + cc;   // Y = true
            float wA, wB;
            ex2_pair(argA, argB, wA, wB);
            SwA += wA;  SxA = fmaf(wA, q.y, SxA);   // x = true  (vT)
            SwB += wB;  SxB = fmaf(wB, q.w, SxB);   // x = pred  (vP)
        }
        part_a[warp][0][lane] = SwA;
        part_a[warp][1][lane] = SxA * MXS;
        part_a[warp][2][lane] = SwB;
        part_a[warp][3][lane] = SxB * MXS;

        if (warp < 7) {
            const int s2b = s1e;
            const int s2e = 92 * warp + 92;
            SwA = 0.f; SxA = 0.f; SwB = 0.f; SxB = 0.f;
            #pragma unroll 4
            for (int idx = s2b; idx < s2e; idx++) {
                float4 q = uv[idx];
                float argA = fmaf(q.w, cb, q.z) + cc;
                float argB = fmaf(q.y, cb, q.x) + cc;
                float wA, wB;
                ex2_pair(argA, argB, wA, wB);
                SwA += wA;  SxA = fmaf(wA, q.y, SxA);
                SwB += wB;  SxB = fmaf(wB, q.w, SxB);
            }
            part_b[warp + 1][0][lane] = SwA;
            part_b[warp + 1][1][lane] = SxA * MXS;
            part_b[warp + 1][2][lane] = SwB;
            part_b[warp + 1][3][lane] = SxB * MXS;
        }
    }
    __syncthreads();

    // ---- Combine per sub-region, publish CONSUMER-MAJOR record ----
    {
        const int s = warp;
        float v0 = part_a[s][0][lane];
        float v1 = part_a[s][1][lane];
        float v2 = part_a[s][2][lane];
        float v3 = part_a[s][3][lane];
        if (s >= 1) {
            v0 += part_b[s][0][lane];
            v1 += part_b[s][1][lane];
            v2 += part_b[s][2][lane];
            v3 += part_b[s][3][lane];
        }
        part_a[s][0][lane] = v0;
        part_a[s][1][lane] = v1;
        part_a[s][2][lane] = v2;
        part_a[s][3][lane] = v3;

        int cc2 = 7 - s;
        int dh = (cc2 >> 2) & 1, dw = (cc2 >> 1) & 1, dd = cc2 & 1;
        int pa = ph - dh; if (pa < 0) pa += 10;
        int pb = pw - dw; if (pb < 0) pb += 10;
        int pc = pd - dd; if (pc < 0) pc += 10;
        int pt = (pa * 10 + pb) * 10 + pc;

        int gb = (pt * 8 + cc2) * 160 + lane;
        g_rec[gb]       = v0;
        g_rec[gb + 32]  = v1;
        g_rec[gb + 64]  = v2;
        g_rec[gb + 96]  = v3;
        if (lane < 4) g_rec[(pt * 8 + cc2) * 160 + 128 + lane] = stats_sm[s][lane];
    }
    __syncthreads();

    // ---- Shift-0 etas (variants 0 and 1); ONE atomic per block ----
    if (warp < 2) {
        const int v0 = warp * 2;
        float Sw = 0.f, Sx = 0.f;
        #pragma unroll
        for (int s = 0; s < 8; s++) { Sw += part_a[s][v0][lane]; Sx += part_a[s][v0 + 1][lane]; }
        float sT = 0.f, sT2 = 0.f, sP = 0.f, sP2 = 0.f;
        #pragma unroll
        for (int s = 0; s < 8; s++) {
            sT += stats_sm[s][0]; sT2 += stats_sm[s][1];
            sP += stats_sm[s][2]; sP2 += stats_sm[s][3];
        }
        float e = eta_value(warp, Sw, Sx, sT, sT2, sP, sP2);
        if (lane == 0) s_eta2[warp] = e;
    }
    __syncthreads();
    if (tid == 0) {
        atomicAdd(&g_sum, (double)s_eta2[0] + (double)s_eta2[1]);
        cudaTriggerProgrammaticLaunchCompletion();
    }
}

__global__ __launch_bounds__(256) void lcr_final_kernel(float* __restrict__ out) {
    const int tid = threadIdx.x;
    const int warp = tid >> 5;
    const int lane = tid & 31;
    const int pt = blockIdx.x * 8 + warp;        // 125 blocks x 8 warps = 1000

    __shared__ float s_eta[8];

    cudaGridDependencySynchronize();

    // Contiguous gather: 8 slots x 5 rows x 32 lanes (one 5KB stream / patch).
    float SwA = 0.f, SxA = 0.f, SwB = 0.f, SxB = 0.f;
    float sT = 0.f, sT2 = 0.f, sP = 0.f, sP2 = 0.f;
    const float* base = &g_rec[pt * 8 * 160];
    #pragma unroll
    for (int cc = 0; cc < 8; cc++) {
        const float* rec = base + cc * 160;
        SwA += rec[lane];
        SxA += rec[32 + lane];
        SwB += rec[64 + lane];
        SxB += rec[96 + lane];
        sT  += rec[128];
        sT2 += rec[129];
        sP  += rec[130];
        sP2 += rec[131];
    }

    // Both etas with one fused 4-value shuffle chain.
    {
        float meanA = sT * (1.0f / (float)W3);
        float varA  = (sT2 - sT * sT * (1.0f / (float)W3)) * (1.0f / (float)(W3 - 1));
        float meanB = sP * (1.0f / (float)W3);
        float varB  = (sP2 - sP * sP * (1.0f / (float)W3)) * (1.0f / (float)(W3 - 1));
        float miA = SxA / (SwA + 1e-5f);
        float miB = SxB / (SwB + 1e-5f);
        float dA = miA - meanA;
        float dB = miB - meanB;
        float numA = SwA * dA * dA, denA = SwA;
        float numB = SwB * dB * dB, denB = SwB;
        #pragma unroll
        for (int o = 16; o; o >>= 1) {
            numA += __shfl_xor_sync(0xffffffffu, numA, o);
            denA += __shfl_xor_sync(0xffffffffu, denA, o);
            numB += __shfl_xor_sync(0xffffffffu, numB, o);
            denB += __shfl_xor_sync(0xffffffffu, denB, o);
        }
        if (lane == 0)
            s_eta[warp] = (numA / denA) / (varA + 1e-5f)
                        + (numB / denB) / (varB + 1e-5f);
    }
    __syncthreads();

    // ---- One atomic per block, then acq_rel completion counter ----
    if (tid == 0) {
        double tot = 0.0;
        #pragma unroll
        for (int w = 0; w < 8; w++) tot += (double)s_eta[w];
        atomicAdd(&g_sum, tot);
        unsigned int old = atom_acqrel_add(&g_count, 1u);
        if (old == 125u - 1u) {
            double s = *((volatile double*)&g_sum);
            out[0] = (float)(-s / 12000.0);
            g_sum = 0.0;      // reset for next graph replay
            g_count = 0;
        }
    }
}

extern "C" void kernel_launch(void* const* d_in, const int* in_sizes, int n_in,
                              void* d_out, int out_size) {
    const float* y_true = (const float*)d_in[0];
    const float* y_pred = (const float*)d_in[1];
    float* out = (float*)d_out;

    lcr_part_kernel<<<NPATCH, 256>>>(y_true, y_pred);

    cudaLaunchConfig_t cfg = {};
    cfg.gridDim = dim3(125, 1, 1);
    cfg.blockDim = dim3(256, 1, 1);
    cfg.dynamicSmemBytes = 0;
    cudaLaunchAttribute attrs[1];
    attrs[0].id = cudaLaunchAttributeProgrammaticStreamSerialization;
    attrs[0].val.programmaticStreamSerializationAllowed = 1;
    cfg.attrs = attrs;
    cfg.numAttrs = 1;
    cudaLaunchKernelEx(&cfg, lcr_final_kernel, out);
}

// round 17
// speedup vs baseline: 1.1618x; 1.0038x over previous
#include <cuda_runtime.h>
#include <cuda_fp16.h>

// LocalCorrRatio, two kernels + PDL, bin-major float4 records, f16x2 exp.
// Kernel 1: block = shift-0 patch; float4 {uT,vT,uP,vP}, u=K*y^2, v=-2K*y;
// both directions' Parzen weights via ONE ex2.approx.f16x2 per voxel (args
// and accumulators fp32). Per-sub-region partials published bin-major into
// the consuming shifted patch's record: g_rec[pt][cc][bin] = float4
// {SwA,SxA,SwB,SxB} (1 STG.128/lane); stats into g_stats2[pt][cc*4+sidx].
// Shift-0 etas -> ONE double atomicAdd; programmatic trigger.
// Kernel 2: 125x256; warp = shifted patch; 8 LDG.128 + 1 LDG.32 per lane;
// ONE atomicAdd per block; acq_rel counter (125); last arriver writes out.

#define NPATCH 1000
#define W3 729
#define DIM 90
#define KEXP2 (-1386.4299343f)    // K = -961 * log2(e)
#define K2N   (2772.8598686f)     // -2K
#define MXS   (1.0f / 2772.8598686f)   // -1/(2K): y = v * MXS
#define KINV  (-1.0f / 1386.4299343f)  // 1/K: y^2 = u * KINV

// Bin-major records: [pt][cc][bin] of float4 {SwA, SxA, SwB, SxB}.
__device__ __align__(16) float4 g_rec[NPATCH * 8 * 32];
// Compact stats: [pt][cc*4 + sidx], sidx in {sumT, sumT2, sumP, sumP2}.
__device__ float g_stats2[NPATCH * 32];
__device__ unsigned int g_count = 0;
__device__ double g_sum = 0.0;

__constant__ int cBASE[8]  = {0, 64, 144, 224, 324, 404, 504, 604};
__constant__ int cSPLIT[8] = {64, 144, 224, 324, 404, 504, 604, 729};

__device__ __forceinline__ unsigned int atom_acqrel_add(unsigned int* a, unsigned int v) {
    unsigned int old;
    asm volatile("atom.acq_rel.gpu.global.add.u32 %0, [%1], %2;"
                 : "=r"(old) : "l"(a), "r"(v) : "memory");
    return old;
}

// Two exp2's with one MUFU op: returns {2^la, 2^ha} (computed in f16).
__device__ __forceinline__ void ex2_pair(float la, float ha, float& lw, float& hw) {
    unsigned int p;
    asm("cvt.rn.f16x2.f32 %0, %1, %2;" : "=r"(p) : "f"(ha), "f"(la));
    asm("ex2.approx.f16x2 %0, %0;" : "+r"(p));
    asm("{\n\t.reg .b16 l, h;\n\t"
        "mov.b32 {l, h}, %2;\n\t"
        "cvt.f32.f16 %0, l;\n\t"
        "cvt.f32.f16 %1, h;\n\t}"
        : "=f"(lw), "=f"(hw) : "r"(p));
}

// Returns eta (valid in lane 0 only).
__device__ __forceinline__ float eta_value(int dir, float Sw, float Sx,
                                           float sT, float sT2, float sP, float sP2) {
    float sx  = (dir == 0) ? sT  : sP;
    float sx2 = (dir == 0) ? sT2 : sP2;
    float mean = sx * (1.0f / (float)W3);
    float var  = (sx2 - sx * sx * (1.0f / (float)W3)) * (1.0f / (float)(W3 - 1));
    float mi = Sx / (Sw + 1e-5f);
    float dm = mi - mean;
    float num = Sw * dm * dm;
    float den = Sw;
    #pragma unroll
    for (int o = 16; o; o >>= 1) {
        num += __shfl_xor_sync(0xffffffffu, num, o);
        den += __shfl_xor_sync(0xffffffffu, den, o);
    }
    return (num / den) / (var + 1e-5f);
}

__global__ __launch_bounds__(256, 8) void lcr_part_kernel(const float* __restrict__ yt,
                                                          const float* __restrict__ yp) {
    const int p = blockIdx.x;
    const int ph = p / 100;
    const int pw = (p / 10) % 10;
    const int pd = p % 10;

    __shared__ __align__(16) float4 uv[W3];    // {uT, vT, uP, vP}
    __shared__ float part_a[8][4][32];
    __shared__ float part_b[8][4][32];
    __shared__ float stats_sm[8][4];
    __shared__ float s_eta2[2];

    const int tid = threadIdx.x;
    const int warp = tid >> 5;
    const int lane = tid & 31;
    const float cb = (float)lane * (1.0f / 31.0f);
    const float cc = KEXP2 * cb * cb;

    // ---- Load patch into sub-region-major order; precompute u,v ----
    for (int idx = tid; idx < W3; idx += 256) {
        int i = idx / 81;
        int r = idx - i * 81;
        int j = r / 9;
        int k = r - j * 9;
        int g = ((ph * 9 + i) * DIM + (pw * 9 + j)) * DIM + (pd * 9 + k);
        float tv = yt[g];
        float pv = yp[g];
        int sh = (i >= 4), sw_ = (j >= 4), sd_ = (k >= 4);
        int s = (sh << 2) | (sw_ << 1) | sd_;
        int ii = i - (sh ? 4 : 0);
        int jj = j - (sw_ ? 4 : 0);
        int kk = k - (sd_ ? 4 : 0);
        int nw = sw_ ? 5 : 4;
        int nd = sd_ ? 5 : 4;
        int dest = cBASE[s] + (ii * nw + jj) * nd + kk;
        uv[dest] = make_float4(KEXP2 * tv * tv, K2N * tv,
                               KEXP2 * pv * pv, K2N * pv);
    }
    __syncthreads();

    // ---- Stats for sub-region s == warp (linear recovery from u,v) ----
    {
        int b0 = cBASE[warp];
        int b1 = (warp < 7) ? cBASE[warp + 1] : W3;
        float suT = 0.f, svT = 0.f, suP = 0.f, svP = 0.f;
        for (int idx = b0 + lane; idx < b1; idx += 32) {
            float4 q = uv[idx];
            suT += q.x;  svT += q.y;
            suP += q.z;  svP += q.w;
        }
        #pragma unroll
        for (int o = 16; o; o >>= 1) {
            suT += __shfl_xor_sync(0xffffffffu, suT, o);
            svT += __shfl_xor_sync(0xffffffffu, svT, o);
            suP += __shfl_xor_sync(0xffffffffu, suP, o);
            svP += __shfl_xor_sync(0xffffffffu, svP, o);
        }
        if (lane == 0) {
            stats_sm[warp][0] = svT * MXS;    // sum t
            stats_sm[warp][1] = suT * KINV;   // sum t^2
            stats_sm[warp][2] = svP * MXS;    // sum p
            stats_sm[warp][3] = suP * KINV;   // sum p^2
        }
    }

    // ---- Bin sums: lane = bin; warp range split at one static boundary.
    //      One f16x2 MUFU per voxel computes both directions' weights. ----
    {
        const int s1b = 92 * warp;
        const int s1e = cSPLIT[warp];
        float SwA = 0.f, SxA = 0.f, SwB = 0.f, SxB = 0.f;
        #pragma unroll 4
        for (int idx = s1b; idx < s1e; idx++) {
            float4 q = uv[idx];
            float argA = fmaf(q.w, cb, q.z) + cc;   // Y = pred
            float argB = fmaf(q.y, cb, q.x) + cc;   // Y = true
            float wA, wB;
            ex2_pair(argA, argB, wA, wB);
            SwA += wA;  SxA = fmaf(wA, q.y, SxA);   // x = true  (vT)
            SwB += wB;  SxB = fmaf(wB, q.w, SxB);   // x = pred  (vP)
        }
        part_a[warp][0][lane] = SwA;
        part_a[warp][1][lane] = SxA * MXS;
        part_a[warp][2][lane] = SwB;
        part_a[warp][3][lane] = SxB * MXS;

        if (warp < 7) {
            const int s2b = s1e;
            const int s2e = 92 * warp + 92;
            SwA = 0.f; SxA = 0.f; SwB = 0.f; SxB = 0.f;
            #pragma unroll 4
            for (int idx = s2b; idx < s2e; idx++) {
                float4 q = uv[idx];
                float argA = fmaf(q.w, cb, q.z) + cc;
                float argB = fmaf(q.y, cb, q.x) + cc;
                float wA, wB;
                ex2_pair(argA, argB, wA, wB);
                SwA += wA;  SxA = fmaf(wA, q.y, SxA);
                SwB += wB;  SxB = fmaf(wB, q.w, SxB);
            }
            part_b[warp + 1][0][lane] = SwA;
            part_b[warp + 1][1][lane] = SxA * MXS;
            part_b[warp + 1][2][lane] = SwB;
            part_b[warp + 1][3][lane] = SxB * MXS;
        }
    }
    __syncthreads();

    // ---- Combine per sub-region, publish bin-major float4 record ----
    {
        const int s = warp;
        float v0 = part_a[s][0][lane];
        float v1 = part_a[s][1][lane];
        float v2 = part_a[s][2][lane];
        float v3 = part_a[s][3][lane];
        if (s >= 1) {
            v0 += part_b[s][0][lane];
            v1 += part_b[s][1][lane];
            v2 += part_b[s][2][lane];
            v3 += part_b[s][3][lane];
        }
        part_a[s][0][lane] = v0;
        part_a[s][1][lane] = v1;
        part_a[s][2][lane] = v2;
        part_a[s][3][lane] = v3;

        int cc2 = 7 - s;
        int dh = (cc2 >> 2) & 1, dw = (cc2 >> 1) & 1, dd = cc2 & 1;
        int pa = ph - dh; if (pa < 0) pa += 10;
        int pb = pw - dw; if (pb < 0) pb += 10;
        int pc = pd - dd; if (pc < 0) pc += 10;
        int pt = (pa * 10 + pb) * 10 + pc;

        g_rec[(pt * 8 + cc2) * 32 + lane] = make_float4(v0, v1, v2, v3);
        if (lane < 4) g_stats2[pt * 32 + cc2 * 4 + lane] = stats_sm[s][lane];
    }
    __syncthreads();

    // ---- Shift-0 etas (variants 0 and 1); ONE atomic per block ----
    if (warp < 2) {
        const int v0 = warp * 2;
        float Sw = 0.f, Sx = 0.f;
        #pragma unroll
        for (int s = 0; s < 8; s++) { Sw += part_a[s][v0][lane]; Sx += part_a[s][v0 + 1][lane]; }
        float sT = 0.f, sT2 = 0.f, sP = 0.f, sP2 = 0.f;
        #pragma unroll
        for (int s = 0; s < 8; s++) {
            sT += stats_sm[s][0]; sT2 += stats_sm[s][1];
            sP += stats_sm[s][2]; sP2 += stats_sm[s][3];
        }
        float e = eta_value(warp, Sw, Sx, sT, sT2, sP, sP2);
        if (lane == 0) s_eta2[warp] = e;
    }
    __syncthreads();
    if (tid == 0) {
        atomicAdd(&g_sum, (double)s_eta2[0] + (double)s_eta2[1]);
        cudaTriggerProgrammaticLaunchCompletion();
    }
}

__global__ __launch_bounds__(256) void lcr_final_kernel(float* __restrict__ out) {
    const int tid = threadIdx.x;
    const int warp = tid >> 5;
    const int lane = tid & 31;
    const int pt = blockIdx.x * 8 + warp;        // 125 blocks x 8 warps = 1000

    __shared__ float s_eta[8];

    cudaGridDependencySynchronize();

    // Bin-major gather: 8 LDG.128 per lane (4KB contiguous per warp) + 1 stat.
    float SwA = 0.f, SxA = 0.f, SwB = 0.f, SxB = 0.f;
    const float4* base = &g_rec[pt * 8 * 32];
    #pragma unroll
    for (int cc = 0; cc < 8; cc++) {
        float4 r = base[cc * 32 + lane];
        SwA += r.x;  SxA += r.y;  SwB += r.z;  SxB += r.w;
    }
    // Stats: lane = cc*4 + sidx; sum lanes sharing sidx, then broadcast.
    float st4 = g_stats2[pt * 32 + lane];
    #pragma unroll
    for (int o = 16; o >= 4; o >>= 1) st4 += __shfl_xor_sync(0xffffffffu, st4, o);
    float sT  = __shfl_sync(0xffffffffu, st4, 0);
    float sT2 = __shfl_sync(0xffffffffu, st4, 1);
    float sP  = __shfl_sync(0xffffffffu, st4, 2);
    float sP2 = __shfl_sync(0xffffffffu, st4, 3);

    // Both etas with one fused 4-value shuffle chain.
    {
        float meanA = sT * (1.0f / (float)W3);
        float varA  = (sT2 - sT * sT * (1.0f / (float)W3)) * (1.0f / (float)(W3 - 1));
        float meanB = sP * (1.0f / (float)W3);
        float varB  = (sP2 - sP * sP * (1.0f / (float)W3)) * (1.0f / (float)(W3 - 1));
        float miA = SxA / (SwA + 1e-5f);
        float miB = SxB / (SwB + 1e-5f);
        float dA = miA - meanA;
        float dB = miB - meanB;
        float numA = SwA * dA * dA, denA = SwA;
        float numB = SwB * dB * dB, denB = SwB;
        #pragma unroll
        for (int o = 16; o; o >>= 1) {
            numA += __shfl_xor_sync(0xffffffffu, numA, o);
            denA += __shfl_xor_sync(0xffffffffu, denA, o);
            numB += __shfl_xor_sync(0xffffffffu, numB, o);
            denB += __shfl_xor_sync(0xffffffffu, denB, o);
        }
        if (lane == 0)
            s_eta[warp] = (numA / denA) / (varA + 1e-5f)
                        + (numB / denB) / (varB + 1e-5f);
    }
    __syncthreads();

    // ---- One atomic per block, then acq_rel completion counter ----
    if (tid == 0) {
        double tot = 0.0;
        #pragma unroll
        for (int w = 0; w < 8; w++) tot += (double)s_eta[w];
        atomicAdd(&g_sum, tot);
        unsigned int old = atom_acqrel_add(&g_count, 1u);
        if (old == 125u - 1u) {
            double s = *((volatile double*)&g_sum);
            out[0] = (float)(-s / 12000.0);
            g_sum = 0.0;      // reset for next graph replay
            g_count = 0;
        }
    }
}

extern "C" void kernel_launch(void* const* d_in, const int* in_sizes, int n_in,
                              void* d_out, int out_size) {
    const float* y_true = (const float*)d_in[0];
    const float* y_pred = (const float*)d_in[1];
    float* out = (float*)d_out;

    lcr_part_kernel<<<NPATCH, 256>>>(y_true, y_pred);

    cudaLaunchConfig_t cfg = {};
    cfg.gridDim = dim3(125, 1, 1);
    cfg.blockDim = dim3(256, 1, 1);
    cfg.dynamicSmemBytes = 0;
    cudaLaunchAttribute attrs[1];
    attrs[0].id = cudaLaunchAttributeProgrammaticStreamSerialization;
    attrs[0].val.programmaticStreamSerializationAllowed = 1;
    cfg.attrs = attrs;
    cfg.numAttrs = 1;
    cudaLaunchKernelEx(&cfg, lcr_final_kernel, out);
}